// round 4
// baseline (speedup 1.0000x reference)
#include <cuda_runtime.h>
#include <cstdint>

// Problem constants (fixed by the dataset).
#define NN 100000
#define EE 1600000
#define EPE (EE + NN)          // edges incl. self-loops
#define NEG_SLOPE 0.2f
#define NB 98                  // scan blocks: ceil(100000/1024)

// ---------------------------------------------------------------------------
// Scratch (static device globals; no allocations allowed).
// Split xl / xr tables: the per-edge gather touches only xl, so the gather
// working set halves and (layer 2: 102 MB) fits in the 126 MB L2.
// ---------------------------------------------------------------------------
__device__ float g_xl1[(size_t)NN * 64];
__device__ float g_xr1[(size_t)NN * 64];
__device__ float g_agg1[(size_t)NN * 64];    // layer1 output (pre bias/relu)
__device__ float g_xl2[(size_t)NN * 256];
__device__ float g_xr2[(size_t)NN * 256];
__device__ int   g_src[EPE], g_dst[EPE];     // decoded edges (+self loops)
__device__ int   g_ssrc[EPE];                // srcs sorted by dst (CSR payload)
__device__ int   g_deg[NN], g_cur[NN];
__device__ int   g_off[NN + 1];              // CSR row offsets
__device__ int   g_bsum[NB], g_boff[NB];
__device__ int   g_is64;

typedef unsigned long long u64;
__device__ __forceinline__ u64 pack2(float x, float y) {
    u64 r; asm("mov.b64 %0, {%1,%2};" : "=l"(r) : "f"(x), "f"(y)); return r;
}
__device__ __forceinline__ u64 ffma2(u64 a, u64 b, u64 c) {
    u64 d; asm("fma.rn.f32x2 %0, %1, %2, %3;" : "=l"(d) : "l"(a), "l"(b), "l"(c)); return d;
}
__device__ __forceinline__ float2 unpack2(u64 v) {
    float2 f; asm("mov.b64 {%0,%1}, %2;" : "=f"(f.x), "=f"(f.y) : "l"(v)); return f;
}

// ---------------------------------------------------------------------------
// Meta init: zero degree/cursor counters, set dtype flag default.
// ---------------------------------------------------------------------------
__global__ void zero_meta_kernel() {
    int i = blockIdx.x * blockDim.x + threadIdx.x;
    if (i < NN) { g_deg[i] = 0; g_cur[i] = 0; }
    if (i == 0) g_is64 = 1;
}

#define DETECT_SAMPLES 65536
__global__ void detect_kernel(const long long* __restrict__ ei) {
    int i = blockIdx.x * blockDim.x + threadIdx.x;
    if (i < DETECT_SAMPLES) {
        long long v = ei[i];
        if (v < 0 || v >= NN) g_is64 = 0;
    }
}

// Decode edges (either dtype), append self-loops, histogram degrees by dst.
__global__ void convert_hist_kernel(const void* __restrict__ ei) {
    int i = blockIdx.x * blockDim.x + threadIdx.x;
    if (i >= EPE) return;
    int s, d;
    if (i >= EE) { s = d = i - EE; }
    else if (g_is64) {
        s = (int)((const long long*)ei)[i];
        d = (int)((const long long*)ei)[EE + i];
    } else {
        s = ((const int*)ei)[i];
        d = ((const int*)ei)[EE + i];
    }
    g_src[i] = s; g_dst[i] = d;
    atomicAdd(&g_deg[d], 1);
}

// ---------------------------------------------------------------------------
// Exclusive prefix scan of g_deg -> g_off (3 kernels).
// ---------------------------------------------------------------------------
__global__ void scan1_kernel() {          // per-block sums
    __shared__ int sm[1024];
    int t = threadIdx.x, i = blockIdx.x * 1024 + t;
    sm[t] = (i < NN) ? g_deg[i] : 0;
    __syncthreads();
    for (int ofs = 512; ofs > 0; ofs >>= 1) {
        if (t < ofs) sm[t] += sm[t + ofs];
        __syncthreads();
    }
    if (t == 0) g_bsum[blockIdx.x] = sm[0];
}

__global__ void scan2_kernel() {          // serial scan of 98 block sums
    if (threadIdx.x == 0) {
        int run = 0;
        for (int b = 0; b < NB; b++) { g_boff[b] = run; run += g_bsum[b]; }
        g_off[NN] = EPE;
    }
}

__global__ void scan3_kernel() {          // block exclusive scan + add offset
    __shared__ int sm[1024];
    int t = threadIdx.x, i = blockIdx.x * 1024 + t;
    int v = (i < NN) ? g_deg[i] : 0;
    sm[t] = v;
    __syncthreads();
    for (int ofs = 1; ofs < 1024; ofs <<= 1) {
        int x = (t >= ofs) ? sm[t - ofs] : 0;
        __syncthreads();
        sm[t] += x;
        __syncthreads();
    }
    if (i < NN) g_off[i] = g_boff[blockIdx.x] + sm[t] - v;
}

__global__ void scatter_kernel() {        // bucket srcs by dst
    int i = blockIdx.x * blockDim.x + threadIdx.x;
    if (i >= EPE) return;
    int d = g_dst[i];
    int pos = g_off[d] + atomicAdd(&g_cur[d], 1);
    g_ssrc[pos] = g_src[i];
}

// ---------------------------------------------------------------------------
// Dual GEMM with packed f32x2 FMA, split outputs:
//   col j < JH:  Yl[row][j]      = X[row] @ W1[:,j]      + b1[j]
//   col j >= JH: Yr[row][j-JH]   = X[row] @ W2[:,j-JH]   + b2[j-JH]
//   X: n x 64 (optional fused relu(X + preBias)); W1,W2: 64 x JH row-major.
// Block 256 threads, 32-row x 128-col tile.
// ---------------------------------------------------------------------------
__global__ void gemm_dual_kernel(const float* __restrict__ X, int n, int JH,
                                 const float* __restrict__ W1, const float* __restrict__ b1,
                                 const float* __restrict__ W2, const float* __restrict__ b2,
                                 const float* __restrict__ preBias,
                                 float* __restrict__ Yl, float* __restrict__ Yr) {
    __shared__ float Wsm[64 * 128];
    __shared__ float Xs[32 * 64];
    const int tid = threadIdx.x;
    const int jt = blockIdx.y;
    const int row0 = blockIdx.x * 32;

#pragma unroll
    for (int t = 0; t < 32; t++) {
        int i = tid + t * 256;
        int k = i >> 7, jj = i & 127;
        int j = jt * 128 + jj;
        Wsm[i] = (j < JH) ? W1[k * JH + j] : W2[k * JH + (j - JH)];
    }
#pragma unroll
    for (int t = 0; t < 8; t++) {
        int i = tid + t * 256;
        int r = i >> 6, k = i & 63;
        int row = row0 + r;
        float v = (row < n) ? X[(size_t)row * 64 + k] : 0.f;
        if (preBias) { v += preBias[k]; v = fmaxf(v, 0.f); }
        Xs[i] = v;
    }
    __syncthreads();

    const int cg = tid & 31, rg = tid >> 5;
    const int c0 = cg * 4;
    const int rbase = rg * 4;

    u64 bias0, bias1;
    {
        int j = jt * 128 + c0;
        const float* bb = (j < JH) ? (b1 + j) : (b2 + (j - JH));
        bias0 = pack2(bb[0], bb[1]);
        bias1 = pack2(bb[2], bb[3]);
    }
    u64 acc[4][2];
#pragma unroll
    for (int r = 0; r < 4; r++) { acc[r][0] = bias0; acc[r][1] = bias1; }

#pragma unroll
    for (int k = 0; k < 64; k++) {
        const ulonglong2 w = *(const ulonglong2*)&Wsm[k * 128 + c0];
        float x0 = Xs[(rbase + 0) * 64 + k];
        float x1 = Xs[(rbase + 1) * 64 + k];
        float x2 = Xs[(rbase + 2) * 64 + k];
        float x3 = Xs[(rbase + 3) * 64 + k];
        u64 p0 = pack2(x0, x0), p1 = pack2(x1, x1);
        u64 p2 = pack2(x2, x2), p3 = pack2(x3, x3);
        acc[0][0] = ffma2(p0, w.x, acc[0][0]); acc[0][1] = ffma2(p0, w.y, acc[0][1]);
        acc[1][0] = ffma2(p1, w.x, acc[1][0]); acc[1][1] = ffma2(p1, w.y, acc[1][1]);
        acc[2][0] = ffma2(p2, w.x, acc[2][0]); acc[2][1] = ffma2(p2, w.y, acc[2][1]);
        acc[3][0] = ffma2(p3, w.x, acc[3][0]); acc[3][1] = ffma2(p3, w.y, acc[3][1]);
    }

    int j = jt * 128 + c0;
    float* Yb;
    int jj;
    if (j < JH) { Yb = Yl; jj = j; } else { Yb = Yr; jj = j - JH; }
#pragma unroll
    for (int r = 0; r < 4; r++) {
        int row = row0 + rbase + r;
        if (row < n) {
            float2 lo = unpack2(acc[r][0]), hi = unpack2(acc[r][1]);
            *(float4*)&Yb[(size_t)row * JH + jj] =
                make_float4(lo.x, lo.y, hi.x, hi.y);
        }
    }
}

// ---------------------------------------------------------------------------
// Fused layer-1 edge pass: warp per dst.
//   out1[d][c] = (sum_e ex_e * xl1[s_e][c]) / (sum_e ex_e)
// Lane l holds channels {2l, 2l+1}; head h = l>>3 (8 lanes/head).
// ---------------------------------------------------------------------------
__global__ void fused1_kernel(const float* __restrict__ att) {
    int d = blockIdx.x * 8 + (threadIdx.x >> 5);
    if (d >= NN) return;
    int lane = threadIdx.x & 31;

    float2 xr = *(const float2*)(g_xr1 + (size_t)d * 64 + lane * 2);
    float a0 = __ldg(att + lane * 2), a1 = __ldg(att + lane * 2 + 1);

    int e0 = g_off[d], e1 = g_off[d + 1];
    float acc0 = 0.f, acc1 = 0.f, den = 0.f;
    for (int e = e0; e < e1; e++) {
        int s = g_ssrc[e];
        float2 xl = *(const float2*)(g_xl1 + (size_t)s * 64 + lane * 2);
        float v0 = xl.x + xr.x; v0 = v0 > 0.f ? v0 : NEG_SLOPE * v0;
        float v1 = xl.y + xr.y; v1 = v1 > 0.f ? v1 : NEG_SLOPE * v1;
        float sc = v0 * a0 + v1 * a1;
        sc += __shfl_xor_sync(0xffffffffu, sc, 1);
        sc += __shfl_xor_sync(0xffffffffu, sc, 2);
        sc += __shfl_xor_sync(0xffffffffu, sc, 4);
        float ex = __expf(sc);
        acc0 += ex * xl.x; acc1 += ex * xl.y; den += ex;
    }
    float inv = 1.f / (den + 1e-16f);
    *(float2*)(g_agg1 + (size_t)d * 64 + lane * 2) = make_float2(acc0 * inv, acc1 * inv);
}

// ---------------------------------------------------------------------------
// Fused layer-2 edge pass + head-mean + bias + relu -> final output.
// Warp per dst; lane l holds channels {8l .. 8l+7} of 256 (head h = l>>3).
// ---------------------------------------------------------------------------
__global__ void fused2_kernel(const float* __restrict__ att,
                              const float* __restrict__ bo2,
                              float* __restrict__ out) {
    int d = blockIdx.x * 8 + (threadIdx.x >> 5);
    if (d >= NN) return;
    int lane = threadIdx.x & 31;

    const float4* xrp = (const float4*)(g_xr2 + (size_t)d * 256 + lane * 8);
    float4 xr0 = xrp[0], xr1 = xrp[1];
    float4 at0 = *(const float4*)(att + lane * 8);
    float4 at1 = *(const float4*)(att + lane * 8 + 4);

    float acc[8];
#pragma unroll
    for (int j = 0; j < 8; j++) acc[j] = 0.f;
    float den = 0.f;

    int e0 = g_off[d], e1 = g_off[d + 1];
    for (int e = e0; e < e1; e++) {
        int s = g_ssrc[e];
        const float4* xlp = (const float4*)(g_xl2 + (size_t)s * 256 + lane * 8);
        float4 v0 = xlp[0], v1 = xlp[1];
        float t, sc = 0.f;
        t = v0.x + xr0.x; t = t > 0.f ? t : NEG_SLOPE * t; sc += t * at0.x;
        t = v0.y + xr0.y; t = t > 0.f ? t : NEG_SLOPE * t; sc += t * at0.y;
        t = v0.z + xr0.z; t = t > 0.f ? t : NEG_SLOPE * t; sc += t * at0.z;
        t = v0.w + xr0.w; t = t > 0.f ? t : NEG_SLOPE * t; sc += t * at0.w;
        t = v1.x + xr1.x; t = t > 0.f ? t : NEG_SLOPE * t; sc += t * at1.x;
        t = v1.y + xr1.y; t = t > 0.f ? t : NEG_SLOPE * t; sc += t * at1.y;
        t = v1.z + xr1.z; t = t > 0.f ? t : NEG_SLOPE * t; sc += t * at1.z;
        t = v1.w + xr1.w; t = t > 0.f ? t : NEG_SLOPE * t; sc += t * at1.w;
        sc += __shfl_xor_sync(0xffffffffu, sc, 1);
        sc += __shfl_xor_sync(0xffffffffu, sc, 2);
        sc += __shfl_xor_sync(0xffffffffu, sc, 4);
        float ex = __expf(sc);
        den += ex;
        acc[0] += ex * v0.x; acc[1] += ex * v0.y; acc[2] += ex * v0.z; acc[3] += ex * v0.w;
        acc[4] += ex * v1.x; acc[5] += ex * v1.y; acc[6] += ex * v1.z; acc[7] += ex * v1.w;
    }

    float inv = 1.f / (den + 1e-16f);
    float nv[8];
#pragma unroll
    for (int j = 0; j < 8; j++) {
        float v = acc[j] * inv;
        v += __shfl_xor_sync(0xffffffffu, v, 8);
        v += __shfl_xor_sync(0xffffffffu, v, 16);
        nv[j] = v;
    }
    if (lane < 8) {
        int c = lane * 8;
        float4 o0, o1;
        o0.x = fmaxf(0.25f * nv[0] + __ldg(bo2 + c + 0), 0.f);
        o0.y = fmaxf(0.25f * nv[1] + __ldg(bo2 + c + 1), 0.f);
        o0.z = fmaxf(0.25f * nv[2] + __ldg(bo2 + c + 2), 0.f);
        o0.w = fmaxf(0.25f * nv[3] + __ldg(bo2 + c + 3), 0.f);
        o1.x = fmaxf(0.25f * nv[4] + __ldg(bo2 + c + 4), 0.f);
        o1.y = fmaxf(0.25f * nv[5] + __ldg(bo2 + c + 5), 0.f);
        o1.z = fmaxf(0.25f * nv[6] + __ldg(bo2 + c + 6), 0.f);
        o1.w = fmaxf(0.25f * nv[7] + __ldg(bo2 + c + 7), 0.f);
        *(float4*)(out + (size_t)d * 64 + c) = o0;
        *(float4*)(out + (size_t)d * 64 + c + 4) = o1;
    }
}

// ---------------------------------------------------------------------------
// Launch
// ---------------------------------------------------------------------------
extern "C" void kernel_launch(void* const* d_in, const int* in_sizes, int n_in,
                              void* d_out, int out_size) {
    const float* x   = (const float*)d_in[0];
    const void*  ei  = d_in[1];
    // d_in[2]: frame_mask (unused)
    const float* Wl1 = (const float*)d_in[3];
    const float* bl1 = (const float*)d_in[4];
    const float* Wr1 = (const float*)d_in[5];
    const float* br1 = (const float*)d_in[6];
    const float* att1 = (const float*)d_in[7];
    const float* bo1 = (const float*)d_in[8];
    const float* Wl2 = (const float*)d_in[9];
    const float* bl2 = (const float*)d_in[10];
    const float* Wr2 = (const float*)d_in[11];
    const float* br2 = (const float*)d_in[12];
    const float* att2 = (const float*)d_in[13];
    const float* bo2 = (const float*)d_in[14];
    float* out = (float*)d_out;

    float *p_xl1, *p_xr1, *p_agg1, *p_xl2, *p_xr2;
    cudaGetSymbolAddress((void**)&p_xl1, g_xl1);
    cudaGetSymbolAddress((void**)&p_xr1, g_xr1);
    cudaGetSymbolAddress((void**)&p_agg1, g_agg1);
    cudaGetSymbolAddress((void**)&p_xl2, g_xl2);
    cudaGetSymbolAddress((void**)&p_xr2, g_xr2);

    // CSR build (sorted by dst)
    zero_meta_kernel<<<(NN + 255) / 256, 256>>>();
    detect_kernel<<<(DETECT_SAMPLES + 255) / 256, 256>>>((const long long*)ei);
    convert_hist_kernel<<<(EPE + 255) / 256, 256>>>(ei);
    scan1_kernel<<<NB, 1024>>>();
    scan2_kernel<<<1, 32>>>();
    scan3_kernel<<<NB, 1024>>>();
    scatter_kernel<<<(EPE + 255) / 256, 256>>>();

    // Layer 1
    {
        dim3 grid((NN + 31) / 32, 1);
        gemm_dual_kernel<<<grid, 256>>>(x, NN, 64, Wl1, bl1, Wr1, br1, nullptr,
                                        p_xl1, p_xr1);
    }
    fused1_kernel<<<(NN + 7) / 8, 256>>>(att1);

    // Layer 2 (relu(agg1 + bo1) folded into GEMM input load)
    {
        dim3 grid((NN + 31) / 32, 4);
        gemm_dual_kernel<<<grid, 256>>>(p_agg1, NN, 256, Wl2, bl2, Wr2, br2, bo1,
                                        p_xl2, p_xr2);
    }
    fused2_kernel<<<(NN + 7) / 8, 256>>>(att2, bo2, out);
}

// round 5
// speedup vs baseline: 1.1563x; 1.1563x over previous
#include <cuda_runtime.h>
#include <cstdint>

// Problem constants (fixed by the dataset).
#define NN 100000
#define EE 1600000
#define EPE (EE + NN)          // edges incl. self-loops
#define NEG_SLOPE 0.2f
#define NB 98                  // scan blocks: ceil(100000/1024)
#define DETECT_SAMPLES 65536

// ---------------------------------------------------------------------------
// Scratch (static device globals; no allocations allowed).
// ---------------------------------------------------------------------------
__device__ float g_xl1[(size_t)NN * 64];
__device__ float g_xr1[(size_t)NN * 64];
__device__ float g_agg1[(size_t)NN * 64];    // layer1 output (pre bias/relu)
__device__ float g_xl2[(size_t)NN * 256];
__device__ float g_xr2[(size_t)NN * 256];
__device__ int   g_ssrc[EPE];                // srcs sorted by dst (CSR payload)
__device__ int   g_deg[NN], g_cur[NN];
__device__ int   g_off[NN + 1];              // CSR row offsets
__device__ int   g_bsum[NB];
__device__ int   g_not64;                    // 1 if edge_index buffer is int32

typedef unsigned long long u64;
__device__ __forceinline__ u64 pack2(float x, float y) {
    u64 r; asm("mov.b64 %0, {%1,%2};" : "=l"(r) : "f"(x), "f"(y)); return r;
}
__device__ __forceinline__ u64 ffma2(u64 a, u64 b, u64 c) {
    u64 d; asm("fma.rn.f32x2 %0, %1, %2, %3;" : "=l"(d) : "l"(a), "l"(b), "l"(c)); return d;
}
__device__ __forceinline__ float2 unpack2(u64 v) {
    float2 f; asm("mov.b64 {%0,%1}, %2;" : "=f"(f.x), "=f"(f.y) : "l"(v)); return f;
}

// ---------------------------------------------------------------------------
// CSR build: init -> detect -> hist -> scan1 -> scan3 -> scatter
// ---------------------------------------------------------------------------
__global__ void init_kernel() {
    int i = blockIdx.x * blockDim.x + threadIdx.x;
    if (i < NN) { g_deg[i] = 1; g_cur[i] = 0; }   // deg=1: self-loop
    if (i == 0) { g_not64 = 0; g_off[NN] = EPE; }
}

__global__ void detect_kernel(const long long* __restrict__ ei) {
    int i = blockIdx.x * blockDim.x + threadIdx.x;
    if (i < DETECT_SAMPLES) {
        long long v = ei[i];
        if (v < 0 || v >= NN) g_not64 = 1;
    }
}

__global__ void hist_kernel(const void* __restrict__ ei) {
    int i = blockIdx.x * blockDim.x + threadIdx.x;
    if (i >= EE) return;
    int d = (g_not64 == 0) ? (int)((const long long*)ei)[EE + i]
                           : ((const int*)ei)[EE + i];
    atomicAdd(&g_deg[d], 1);
}

__global__ void scan1_kernel() {          // per-block sums of g_deg
    __shared__ int sm[1024];
    int t = threadIdx.x, i = blockIdx.x * 1024 + t;
    sm[t] = (i < NN) ? g_deg[i] : 0;
    __syncthreads();
    for (int ofs = 512; ofs > 0; ofs >>= 1) {
        if (t < ofs) sm[t] += sm[t + ofs];
        __syncthreads();
    }
    if (t == 0) g_bsum[blockIdx.x] = sm[0];
}

__global__ void scan3_kernel() {          // block scan + cross-block base
    __shared__ int sm[1024];
    int t = threadIdx.x, b = blockIdx.x;
    // base = sum of g_bsum[0..b)
    sm[t] = (t < NB && t < b) ? g_bsum[t] : 0;
    __syncthreads();
    for (int ofs = 512; ofs > 0; ofs >>= 1) {
        if (t < ofs) sm[t] += sm[t + ofs];
        __syncthreads();
    }
    int base = sm[0];
    __syncthreads();
    int i = b * 1024 + t;
    int v = (i < NN) ? g_deg[i] : 0;
    sm[t] = v;
    __syncthreads();
    for (int ofs = 1; ofs < 1024; ofs <<= 1) {
        int x = (t >= ofs) ? sm[t - ofs] : 0;
        __syncthreads();
        sm[t] += x;
        __syncthreads();
    }
    if (i < NN) g_off[i] = base + sm[t] - v;
}

__global__ void scatter_kernel(const void* __restrict__ ei) {
    int i = blockIdx.x * blockDim.x + threadIdx.x;
    if (i >= EPE) return;
    int s, d;
    if (i >= EE) { s = d = i - EE; }
    else if (g_not64 == 0) {
        s = (int)((const long long*)ei)[i];
        d = (int)((const long long*)ei)[EE + i];
    } else {
        s = ((const int*)ei)[i];
        d = ((const int*)ei)[EE + i];
    }
    int pos = g_off[d] + atomicAdd(&g_cur[d], 1);
    g_ssrc[pos] = s;
}

// ---------------------------------------------------------------------------
// Dual GEMM, f32x2, LDS-light tiling: 64 rows x 128 cols per block (256 thr),
// 8 rows x 4 cols per thread.  Split outputs Yl (cols<JH) / Yr (cols>=JH).
//   X: n x 64 (optional fused relu(X + preBias)); W1,W2: 64 x JH row-major.
// ---------------------------------------------------------------------------
__global__ void __launch_bounds__(256)
gemm_dual_kernel(const float* __restrict__ X, int n, int JH,
                 const float* __restrict__ W1, const float* __restrict__ b1,
                 const float* __restrict__ W2, const float* __restrict__ b2,
                 const float* __restrict__ preBias,
                 float* __restrict__ Yl, float* __restrict__ Yr) {
    __shared__ float Wsm[64 * 128];   // [k][col]  32 KB
    __shared__ float Xs[64 * 64];     // [row][k]  16 KB
    const int tid = threadIdx.x;
    const int jt = blockIdx.y;
    const int row0 = blockIdx.x * 64;

#pragma unroll
    for (int t = 0; t < 32; t++) {
        int i = tid + t * 256;
        int k = i >> 7, jj = i & 127;
        int j = jt * 128 + jj;
        Wsm[i] = (j < JH) ? W1[k * JH + j] : W2[k * JH + (j - JH)];
    }
#pragma unroll
    for (int t = 0; t < 4; t++) {
        int i = tid + t * 256;            // float4 index (1024 total)
        int r = i >> 4, kq = (i & 15) * 4;
        int row = row0 + r;
        float4 v = make_float4(0.f, 0.f, 0.f, 0.f);
        if (row < n) {
            v = *(const float4*)&X[(size_t)row * 64 + kq];
            if (preBias) {
                v.x = fmaxf(v.x + preBias[kq + 0], 0.f);
                v.y = fmaxf(v.y + preBias[kq + 1], 0.f);
                v.z = fmaxf(v.z + preBias[kq + 2], 0.f);
                v.w = fmaxf(v.w + preBias[kq + 3], 0.f);
            }
        }
        *(float4*)&Xs[r * 64 + kq] = v;
    }
    __syncthreads();

    const int cg = tid & 31, wrp = tid >> 5;
    const int c0 = cg * 4;
    const int r0 = wrp * 8;

    int j = jt * 128 + c0;
    const float* bb = (j < JH) ? (b1 + j) : (b2 + (j - JH));
    u64 b01 = pack2(bb[0], bb[1]), b23 = pack2(bb[2], bb[3]);
    u64 acc[8][2];
#pragma unroll
    for (int r = 0; r < 8; r++) { acc[r][0] = b01; acc[r][1] = b23; }

#pragma unroll
    for (int kk = 0; kk < 64; kk += 4) {
        ulonglong2 w[4];
#pragma unroll
        for (int q = 0; q < 4; q++)
            w[q] = *(const ulonglong2*)&Wsm[(kk + q) * 128 + c0];
#pragma unroll
        for (int r = 0; r < 8; r++) {
            float4 xv = *(const float4*)&Xs[(r0 + r) * 64 + kk];
            u64 p;
            p = pack2(xv.x, xv.x); acc[r][0] = ffma2(p, w[0].x, acc[r][0]); acc[r][1] = ffma2(p, w[0].y, acc[r][1]);
            p = pack2(xv.y, xv.y); acc[r][0] = ffma2(p, w[1].x, acc[r][0]); acc[r][1] = ffma2(p, w[1].y, acc[r][1]);
            p = pack2(xv.z, xv.z); acc[r][0] = ffma2(p, w[2].x, acc[r][0]); acc[r][1] = ffma2(p, w[2].y, acc[r][1]);
            p = pack2(xv.w, xv.w); acc[r][0] = ffma2(p, w[3].x, acc[r][0]); acc[r][1] = ffma2(p, w[3].y, acc[r][1]);
        }
    }

    float* Yb; int jj;
    if (j < JH) { Yb = Yl; jj = j; } else { Yb = Yr; jj = j - JH; }
#pragma unroll
    for (int r = 0; r < 8; r++) {
        int row = row0 + r0 + r;
        if (row < n) {
            float2 lo = unpack2(acc[r][0]), hi = unpack2(acc[r][1]);
            *(float4*)&Yb[(size_t)row * JH + jj] = make_float4(lo.x, lo.y, hi.x, hi.y);
        }
    }
}

// ---------------------------------------------------------------------------
// Fused layer-1 edge pass: warp per dst, 2-way edge unroll.
// Lane l holds channels {2l, 2l+1}; head h = l>>3 (8 lanes/head).
// ---------------------------------------------------------------------------
__device__ __forceinline__ float lrelu(float v) { return v > 0.f ? v : NEG_SLOPE * v; }

__global__ void fused1_kernel(const float* __restrict__ att) {
    int d = blockIdx.x * 8 + (threadIdx.x >> 5);
    if (d >= NN) return;
    int lane = threadIdx.x & 31;

    float2 xr = *(const float2*)(g_xr1 + (size_t)d * 64 + lane * 2);
    float a0 = __ldg(att + lane * 2), a1 = __ldg(att + lane * 2 + 1);

    int e = g_off[d], e1 = g_off[d + 1];
    float acc0 = 0.f, acc1 = 0.f, den = 0.f;

    for (; e + 2 <= e1; e += 2) {
        int sa = g_ssrc[e], sb = g_ssrc[e + 1];
        float2 xa = __ldg((const float2*)(g_xl1 + (size_t)sa * 64 + lane * 2));
        float2 xb = __ldg((const float2*)(g_xl1 + (size_t)sb * 64 + lane * 2));
        float sca = lrelu(xa.x + xr.x) * a0 + lrelu(xa.y + xr.y) * a1;
        float scb = lrelu(xb.x + xr.x) * a0 + lrelu(xb.y + xr.y) * a1;
        sca += __shfl_xor_sync(0xffffffffu, sca, 1);
        scb += __shfl_xor_sync(0xffffffffu, scb, 1);
        sca += __shfl_xor_sync(0xffffffffu, sca, 2);
        scb += __shfl_xor_sync(0xffffffffu, scb, 2);
        sca += __shfl_xor_sync(0xffffffffu, sca, 4);
        scb += __shfl_xor_sync(0xffffffffu, scb, 4);
        float exa = __expf(sca), exb = __expf(scb);
        den += exa; den += exb;
        acc0 = fmaf(exa, xa.x, acc0); acc0 = fmaf(exb, xb.x, acc0);
        acc1 = fmaf(exa, xa.y, acc1); acc1 = fmaf(exb, xb.y, acc1);
    }
    if (e < e1) {
        int sa = g_ssrc[e];
        float2 xa = __ldg((const float2*)(g_xl1 + (size_t)sa * 64 + lane * 2));
        float sca = lrelu(xa.x + xr.x) * a0 + lrelu(xa.y + xr.y) * a1;
        sca += __shfl_xor_sync(0xffffffffu, sca, 1);
        sca += __shfl_xor_sync(0xffffffffu, sca, 2);
        sca += __shfl_xor_sync(0xffffffffu, sca, 4);
        float exa = __expf(sca);
        den += exa;
        acc0 = fmaf(exa, xa.x, acc0);
        acc1 = fmaf(exa, xa.y, acc1);
    }
    float inv = 1.f / (den + 1e-16f);
    *(float2*)(g_agg1 + (size_t)d * 64 + lane * 2) = make_float2(acc0 * inv, acc1 * inv);
}

// ---------------------------------------------------------------------------
// Fused layer-2 edge pass + head-mean + bias + relu -> final output.
// Warp per dst, 2-way edge unroll; lane l holds channels {8l..8l+7} of 256.
// ---------------------------------------------------------------------------
__global__ void fused2_kernel(const float* __restrict__ att,
                              const float* __restrict__ bo2,
                              float* __restrict__ out) {
    int d = blockIdx.x * 8 + (threadIdx.x >> 5);
    if (d >= NN) return;
    int lane = threadIdx.x & 31;

    const float4* xrp = (const float4*)(g_xr2 + (size_t)d * 256 + lane * 8);
    float4 xr0 = xrp[0], xr1 = xrp[1];
    float4 at0 = *(const float4*)(att + lane * 8);
    float4 at1 = *(const float4*)(att + lane * 8 + 4);

    float acc[8];
#pragma unroll
    for (int q = 0; q < 8; q++) acc[q] = 0.f;
    float den = 0.f;

    int e = g_off[d], e1 = g_off[d + 1];

    for (; e + 2 <= e1; e += 2) {
        int sa = g_ssrc[e], sb = g_ssrc[e + 1];
        const float4* pa = (const float4*)(g_xl2 + (size_t)sa * 256 + lane * 8);
        const float4* pb = (const float4*)(g_xl2 + (size_t)sb * 256 + lane * 8);
        float4 a0 = __ldg(pa), a1 = __ldg(pa + 1);
        float4 b0 = __ldg(pb), b1 = __ldg(pb + 1);

        float sca = lrelu(a0.x + xr0.x) * at0.x + lrelu(a0.y + xr0.y) * at0.y
                  + lrelu(a0.z + xr0.z) * at0.z + lrelu(a0.w + xr0.w) * at0.w
                  + lrelu(a1.x + xr1.x) * at1.x + lrelu(a1.y + xr1.y) * at1.y
                  + lrelu(a1.z + xr1.z) * at1.z + lrelu(a1.w + xr1.w) * at1.w;
        float scb = lrelu(b0.x + xr0.x) * at0.x + lrelu(b0.y + xr0.y) * at0.y
                  + lrelu(b0.z + xr0.z) * at0.z + lrelu(b0.w + xr0.w) * at0.w
                  + lrelu(b1.x + xr1.x) * at1.x + lrelu(b1.y + xr1.y) * at1.y
                  + lrelu(b1.z + xr1.z) * at1.z + lrelu(b1.w + xr1.w) * at1.w;
        sca += __shfl_xor_sync(0xffffffffu, sca, 1);
        scb += __shfl_xor_sync(0xffffffffu, scb, 1);
        sca += __shfl_xor_sync(0xffffffffu, sca, 2);
        scb += __shfl_xor_sync(0xffffffffu, scb, 2);
        sca += __shfl_xor_sync(0xffffffffu, sca, 4);
        scb += __shfl_xor_sync(0xffffffffu, scb, 4);
        float exa = __expf(sca), exb = __expf(scb);
        den += exa; den += exb;
        acc[0] = fmaf(exa, a0.x, acc[0]); acc[1] = fmaf(exa, a0.y, acc[1]);
        acc[2] = fmaf(exa, a0.z, acc[2]); acc[3] = fmaf(exa, a0.w, acc[3]);
        acc[4] = fmaf(exa, a1.x, acc[4]); acc[5] = fmaf(exa, a1.y, acc[5]);
        acc[6] = fmaf(exa, a1.z, acc[6]); acc[7] = fmaf(exa, a1.w, acc[7]);
        acc[0] = fmaf(exb, b0.x, acc[0]); acc[1] = fmaf(exb, b0.y, acc[1]);
        acc[2] = fmaf(exb, b0.z, acc[2]); acc[3] = fmaf(exb, b0.w, acc[3]);
        acc[4] = fmaf(exb, b1.x, acc[4]); acc[5] = fmaf(exb, b1.y, acc[5]);
        acc[6] = fmaf(exb, b1.z, acc[6]); acc[7] = fmaf(exb, b1.w, acc[7]);
    }
    if (e < e1) {
        int sa = g_ssrc[e];
        const float4* pa = (const float4*)(g_xl2 + (size_t)sa * 256 + lane * 8);
        float4 a0 = __ldg(pa), a1 = __ldg(pa + 1);
        float sca = lrelu(a0.x + xr0.x) * at0.x + lrelu(a0.y + xr0.y) * at0.y
                  + lrelu(a0.z + xr0.z) * at0.z + lrelu(a0.w + xr0.w) * at0.w
                  + lrelu(a1.x + xr1.x) * at1.x + lrelu(a1.y + xr1.y) * at1.y
                  + lrelu(a1.z + xr1.z) * at1.z + lrelu(a1.w + xr1.w) * at1.w;
        sca += __shfl_xor_sync(0xffffffffu, sca, 1);
        sca += __shfl_xor_sync(0xffffffffu, sca, 2);
        sca += __shfl_xor_sync(0xffffffffu, sca, 4);
        float exa = __expf(sca);
        den += exa;
        acc[0] = fmaf(exa, a0.x, acc[0]); acc[1] = fmaf(exa, a0.y, acc[1]);
        acc[2] = fmaf(exa, a0.z, acc[2]); acc[3] = fmaf(exa, a0.w, acc[3]);
        acc[4] = fmaf(exa, a1.x, acc[4]); acc[5] = fmaf(exa, a1.y, acc[5]);
        acc[6] = fmaf(exa, a1.z, acc[6]); acc[7] = fmaf(exa, a1.w, acc[7]);
    }

    float inv = 1.f / (den + 1e-16f);
    float nv[8];
#pragma unroll
    for (int q = 0; q < 8; q++) {
        float v = acc[q] * inv;
        v += __shfl_xor_sync(0xffffffffu, v, 8);
        v += __shfl_xor_sync(0xffffffffu, v, 16);
        nv[q] = v;
    }
    if (lane < 8) {
        int c = lane * 8;
        float4 o0, o1;
        o0.x = fmaxf(0.25f * nv[0] + __ldg(bo2 + c + 0), 0.f);
        o0.y = fmaxf(0.25f * nv[1] + __ldg(bo2 + c + 1), 0.f);
        o0.z = fmaxf(0.25f * nv[2] + __ldg(bo2 + c + 2), 0.f);
        o0.w = fmaxf(0.25f * nv[3] + __ldg(bo2 + c + 3), 0.f);
        o1.x = fmaxf(0.25f * nv[4] + __ldg(bo2 + c + 4), 0.f);
        o1.y = fmaxf(0.25f * nv[5] + __ldg(bo2 + c + 5), 0.f);
        o1.z = fmaxf(0.25f * nv[6] + __ldg(bo2 + c + 6), 0.f);
        o1.w = fmaxf(0.25f * nv[7] + __ldg(bo2 + c + 7), 0.f);
        *(float4*)(out + (size_t)d * 64 + c) = o0;
        *(float4*)(out + (size_t)d * 64 + c + 4) = o1;
    }
}

// ---------------------------------------------------------------------------
// Launch
// ---------------------------------------------------------------------------
extern "C" void kernel_launch(void* const* d_in, const int* in_sizes, int n_in,
                              void* d_out, int out_size) {
    const float* x   = (const float*)d_in[0];
    const void*  ei  = d_in[1];
    // d_in[2]: frame_mask (unused)
    const float* Wl1 = (const float*)d_in[3];
    const float* bl1 = (const float*)d_in[4];
    const float* Wr1 = (const float*)d_in[5];
    const float* br1 = (const float*)d_in[6];
    const float* att1 = (const float*)d_in[7];
    const float* bo1 = (const float*)d_in[8];
    const float* Wl2 = (const float*)d_in[9];
    const float* bl2 = (const float*)d_in[10];
    const float* Wr2 = (const float*)d_in[11];
    const float* br2 = (const float*)d_in[12];
    const float* att2 = (const float*)d_in[13];
    const float* bo2 = (const float*)d_in[14];
    float* out = (float*)d_out;

    float *p_xl1, *p_xr1, *p_agg1, *p_xl2, *p_xr2;
    cudaGetSymbolAddress((void**)&p_xl1, g_xl1);
    cudaGetSymbolAddress((void**)&p_xr1, g_xr1);
    cudaGetSymbolAddress((void**)&p_agg1, g_agg1);
    cudaGetSymbolAddress((void**)&p_xl2, g_xl2);
    cudaGetSymbolAddress((void**)&p_xr2, g_xr2);

    // CSR build (sorted by dst)
    init_kernel<<<(NN + 255) / 256, 256>>>();
    detect_kernel<<<(DETECT_SAMPLES + 255) / 256, 256>>>((const long long*)ei);
    hist_kernel<<<(EE + 255) / 256, 256>>>(ei);
    scan1_kernel<<<NB, 1024>>>();
    scan3_kernel<<<NB, 1024>>>();
    scatter_kernel<<<(EPE + 255) / 256, 256>>>(ei);

    // Layer 1
    {
        dim3 grid((NN + 63) / 64, 1);
        gemm_dual_kernel<<<grid, 256>>>(x, NN, 64, Wl1, bl1, Wr1, br1, nullptr,
                                        p_xl1, p_xr1);
    }
    fused1_kernel<<<(NN + 7) / 8, 256>>>(att1);

    // Layer 2 (relu(agg1 + bo1) folded into GEMM input load)
    {
        dim3 grid((NN + 63) / 64, 4);
        gemm_dual_kernel<<<grid, 256>>>(p_agg1, NN, 256, Wl2, bl2, Wr2, br2, bo1,
                                        p_xl2, p_xr2);
    }
    fused2_kernel<<<(NN + 7) / 8, 256>>>(att2, bo2, out);
}